// round 6
// baseline (speedup 1.0000x reference)
#include <cuda_runtime.h>
#include <mma.h>
#include <math.h>
#include <stdint.h>

using namespace nvcuda;

#define BB 8
#define CC 64
#define OO 64
#define HH 128
#define WW 128
#define HWSZ (HH * WW)

#define TILE 16
#define HALO 18
#define NPOS (HALO * HALO)   // 324
#define NTHR 512
#define LDA  336             // padded M (21 tiles of 16), also lda for A / zs

// smem layout (floats)
#define XHI_OFF 0                         // A-hi / x for div: [c][336] col-major
#define XLO_OFF (XHI_OFF + CC * LDA)      // A-lo; later reused as zs [o][336]
#define WHI_OFF (XLO_OFF + CC * LDA)      // B-hi [o][c] (= core layout)
#define WLO_OFF (WHI_OFF + OO * CC)
#define DS_OFF  (WLO_OFF + OO * CC)       // 512 div partials
#define MK_OFF  (DS_OFF + 512)            // 256 mask flags
#define SMEM_FLOATS (MK_OFF + 256)        // 51968 floats = 207,872 B

__global__ __launch_bounds__(NTHR, 1)
void spconv_wmma_kernel(const float* __restrict__ x,
                        const float* __restrict__ core,
                        const float* __restrict__ periphery,
                        const float* __restrict__ threshold,
                        const float* __restrict__ scale,
                        float* __restrict__ out) {
    extern __shared__ float smem[];
    float* xhi  = smem + XHI_OFF;
    float* xlo  = smem + XLO_OFF;
    float* whi  = smem + WHI_OFF;
    float* wlo  = smem + WLO_OFF;
    float* dsum = smem + DS_OFF;
    float* msk  = smem + MK_OFF;

    const int tid = threadIdx.x;
    const int wid = tid >> 5;
    const int b   = blockIdx.z;
    const int bx0 = blockIdx.x * TILE;
    const int by0 = blockIdx.y * TILE;

    // --- stage W hi/lo (core is [o][c] row-major = matrix_b col-major, ldb=64) ---
    for (int i = tid; i < OO * CC; i += NTHR) {
        float v = core[i];
        float h = wmma::__float_to_tf32(v);
        float l = wmma::__float_to_tf32(v - h);
        whi[i] = h;
        wlo[i] = l;
    }

    // --- zero A pad rows 324..335 ---
    for (int i = tid; i < CC * (LDA - NPOS); i += NTHR) {
        int c = i / (LDA - NPOS);
        int r = NPOS + (i - c * (LDA - NPOS));
        xhi[c * LDA + r] = 0.0f;
        xlo[c * LDA + r] = 0.0f;
    }

    // --- stage x halo (zero padded), tf32 hi/lo, col-major [c][336] ---
    const float* xb = x + (size_t)b * CC * HWSZ;
    for (int i = tid; i < CC * NPOS; i += NTHR) {
        int c  = i / NPOS;
        int p  = i - c * NPOS;
        int iy = p / HALO;
        int ix = p - iy * HALO;
        int gy = by0 + iy - 1;
        int gx = bx0 + ix - 1;
        bool inb = ((unsigned)gy < HH) && ((unsigned)gx < WW);
        float v = inb ? xb[(size_t)c * HWSZ + gy * WW + gx] : 0.0f;
        float h = wmma::__float_to_tf32(v);
        float l = wmma::__float_to_tf32(v - h);
        xhi[c * LDA + p] = h;
        xlo[c * LDA + p] = l;
    }
    __syncthreads();

    // --- div partials: 512 threads, 2 per interior position (32 c each) ---
    {
        const int p   = tid & 255;
        const int hlf = tid >> 8;
        const int tx  = p & 15;
        const int ty  = p >> 4;
        const int q0  = (ty + 1) * HALO + (tx + 1);
        float dv = 0.0f;
        const int c0 = hlf * 32;
#pragma unroll 4
        for (int c = c0; c < c0 + 32; c++) {
            const float* xc = xhi + c * LDA;
            float cen = xc[q0];
            float d;
            d = xc[q0 - HALO - 1] - cen; dv = fmaf(d, d, dv);
            d = xc[q0 - HALO    ] - cen; dv = fmaf(d, d, dv);
            d = xc[q0 - HALO + 1] - cen; dv = fmaf(d, d, dv);
            d = xc[q0 - 1       ] - cen; dv = fmaf(d, d, dv);
            d = xc[q0 + 1       ] - cen; dv = fmaf(d, d, dv);
            d = xc[q0 + HALO - 1] - cen; dv = fmaf(d, d, dv);
            d = xc[q0 + HALO    ] - cen; dv = fmaf(d, d, dv);
            d = xc[q0 + HALO + 1] - cen; dv = fmaf(d, d, dv);
        }
        dsum[tid] = dv;
    }

    // --- 3xTF32 wmma GEMM: C[336x64] = A[336x64] * B^T ---
    // warp -> n-tile (wid&3), m-group (wid>>2): tiles t = mg + 4*j, t < 21
    const int ng = wid & 3;
    const int mg = wid >> 2;
    const int ntiles = (mg == 0) ? 6 : 5;

    wmma::fragment<wmma::accumulator, 16, 16, 8, float> Cf[6];
#pragma unroll
    for (int j = 0; j < 6; j++) wmma::fill_fragment(Cf[j], 0.0f);

    {
        wmma::fragment<wmma::matrix_a, 16, 16, 8, wmma::precision::tf32, wmma::col_major> Ah, Al;
        wmma::fragment<wmma::matrix_b, 16, 16, 8, wmma::precision::tf32, wmma::col_major> Bh, Bl;
#pragma unroll
        for (int k = 0; k < 8; k++) {
            const int k0 = k * 8;
            wmma::load_matrix_sync(Bh, whi + ng * 16 * CC + k0, CC);
            wmma::load_matrix_sync(Bl, wlo + ng * 16 * CC + k0, CC);
#pragma unroll
            for (int j = 0; j < 6; j++) {
                if (j < ntiles) {
                    const int m0 = (mg + 4 * j) * 16;
                    wmma::load_matrix_sync(Ah, xhi + k0 * LDA + m0, LDA);
                    wmma::load_matrix_sync(Al, xlo + k0 * LDA + m0, LDA);
                    wmma::mma_sync(Cf[j], Ah, Bh, Cf[j]);
                    wmma::mma_sync(Cf[j], Ah, Bl, Cf[j]);
                    wmma::mma_sync(Cf[j], Al, Bh, Cf[j]);
                }
            }
        }
    }
    __syncthreads();   // all A-lo reads done before zs overwrites it

    // --- store C tiles into zs (reuse xlo region), [o][336] col-major ---
    float* zs = xlo;
#pragma unroll
    for (int j = 0; j < 6; j++) {
        if (j < ntiles) {
            const int m0 = (mg + 4 * j) * 16;
            wmma::store_matrix_sync(zs + ng * 16 * LDA + m0, Cf[j], LDA,
                                    wmma::mem_col_major);
        }
    }

    // --- combine div partials -> mask ---
    if (tid < 256) {
        float dv = dsum[tid] + dsum[tid + 256];
        float t  = (dv - threshold[0]) * scale[0];
        float sg = 1.0f / (1.0f + expf(-t));
        msk[tid] = (sg > 0.5f) ? 1.0f : 0.0f;
    }
    __syncthreads();

    // --- periphery conv + masked select ---
    const float pr0 = periphery[0], pr1 = periphery[1], pr2 = periphery[2],
                pr3 = periphery[3], pr4 = periphery[4], pr5 = periphery[5],
                pr6 = periphery[6], pr7 = periphery[7];
    float* ob = out + (size_t)b * OO * HWSZ;

    for (int i = tid; i < OO * 256; i += NTHR) {
        int o  = i >> 8;
        int p  = i & 255;
        int tx = p & 15;
        int ty = p >> 4;
        int q0 = (ty + 1) * HALO + (tx + 1);
        const float* zo = zs + o * LDA;
        float cen = zo[q0];
        float a;
        a = pr0 * zo[q0 - HALO - 1];
        a = fmaf(pr1, zo[q0 - HALO    ], a);
        a = fmaf(pr2, zo[q0 - HALO + 1], a);
        a = fmaf(pr3, zo[q0 - 1       ], a);
        a = fmaf(pr4, zo[q0 + 1       ], a);
        a = fmaf(pr5, zo[q0 + HALO - 1], a);
        a = fmaf(pr6, zo[q0 + HALO    ], a);
        a = fmaf(pr7, zo[q0 + HALO + 1], a);
        float r = (msk[p] > 0.5f) ? a : cen;
        __stcg(&ob[(size_t)o * HWSZ + (size_t)(by0 + ty) * WW + (bx0 + tx)], r);
    }
}

extern "C" void kernel_launch(void* const* d_in, const int* in_sizes, int n_in,
                              void* d_out, int out_size) {
    const float* x    = (const float*)d_in[0];
    const float* core = (const float*)d_in[1];
    const float* peri = (const float*)d_in[2];
    const float* thr  = (const float*)d_in[3];
    const float* scl  = (const float*)d_in[4];
    float* out = (float*)d_out;

    const int smem = SMEM_FLOATS * sizeof(float);   // 207,872 B
    cudaFuncSetAttribute(spconv_wmma_kernel,
                         cudaFuncAttributeMaxDynamicSharedMemorySize, smem);

    dim3 grid(WW / TILE, HH / TILE, BB);   // 512 CTAs
    spconv_wmma_kernel<<<grid, NTHR, smem>>>(x, core, peri, thr, scl, out);
}

// round 7
// speedup vs baseline: 1.4152x; 1.4152x over previous
#include <cuda_runtime.h>
#include <math.h>

#define BB 8
#define CC 64
#define OO 64
#define HH 128
#define WW 128
#define HWSZ (HH * WW)

#define TX 16
#define TY 8
#define NOUT (TX * TY)        // 128 outputs per CTA
#define HX 18
#define HY 10
#define NPOS (HX * HY)        // 180 halo positions
#define NTHR 384
#define NSLOT 360             // 90 pos-pairs * 4 o-quarters

// smem (floats):
//   ws   [0, 4096)              W^T [c][o]
//   xs   [4096, 4096+11520)     x halo [c][180]; reused as z halo [o][180]
//   dsum [15616, 16000)         384 div partials
//   msk  [16000, 16128)         128 mask flags
#define WS_OFF 0
#define XS_OFF 4096
#define DS_OFF (XS_OFF + CC * NPOS)
#define MK_OFF (DS_OFF + NTHR)
#define SMEM_FLOATS (MK_OFF + NOUT)   // 16128 floats = 64512 B

__global__ __launch_bounds__(NTHR, 2)
void spconv_fused2_kernel(const float* __restrict__ x,
                          const float* __restrict__ core,
                          const float* __restrict__ periphery,
                          const float* __restrict__ threshold,
                          const float* __restrict__ scale,
                          float* __restrict__ out) {
    extern __shared__ float smem[];
    float* ws   = smem + WS_OFF;
    float* xs   = smem + XS_OFF;
    float* dsum = smem + DS_OFF;
    float* msk  = smem + MK_OFF;

    const int tid = threadIdx.x;
    const int b   = blockIdx.z;
    const int bx0 = blockIdx.x * TX;
    const int by0 = blockIdx.y * TY;

    // --- stage W transposed: ws[c][o] = core[o][c] ---
    for (int i = tid; i < OO * CC; i += NTHR) {
        int o = i >> 6, c = i & 63;
        ws[c * 64 + o] = core[i];
    }

    // --- stage x halo tile (zero padded), [c][180] ---
    const float* xb = x + (size_t)b * CC * HWSZ;
    for (int i = tid; i < CC * NPOS; i += NTHR) {   // 30 iters
        int c  = i / NPOS;
        int p  = i - c * NPOS;
        int iy = p / HX;
        int ix = p - iy * HX;
        int gy = by0 + iy - 1;
        int gx = bx0 + ix - 1;
        bool inb = ((unsigned)gy < HH) && ((unsigned)gx < WW);
        xs[i] = inb ? xb[(size_t)c * HWSZ + gy * WW + gx] : 0.0f;
    }
    __syncthreads();

    // --- GEMM: slot = (o-quarter, position-pair); 32 accs/thread ---
    float acc[32];
#pragma unroll
    for (int i = 0; i < 32; i++) acc[i] = 0.0f;

    const int oq = tid / 90;           // 0..3 (tid<360)
    const int pp = tid - oq * 90;      // 0..89
    const bool active = (tid < NSLOT);

    if (active) {
        const float* xpair = xs + 2 * pp;
        const float* wq    = ws + oq * 16;
#pragma unroll 2
        for (int c = 0; c < CC; c++) {
            float2 xv = *reinterpret_cast<const float2*>(xpair + c * NPOS);
            const float4* w4 = reinterpret_cast<const float4*>(wq + c * 64);
#pragma unroll
            for (int i = 0; i < 4; i++) {
                float4 w = w4[i];
                acc[i * 8 + 0] = fmaf(xv.x, w.x, acc[i * 8 + 0]);
                acc[i * 8 + 1] = fmaf(xv.y, w.x, acc[i * 8 + 1]);
                acc[i * 8 + 2] = fmaf(xv.x, w.y, acc[i * 8 + 2]);
                acc[i * 8 + 3] = fmaf(xv.y, w.y, acc[i * 8 + 3]);
                acc[i * 8 + 4] = fmaf(xv.x, w.z, acc[i * 8 + 4]);
                acc[i * 8 + 5] = fmaf(xv.y, w.z, acc[i * 8 + 5]);
                acc[i * 8 + 6] = fmaf(xv.x, w.w, acc[i * 8 + 6]);
                acc[i * 8 + 7] = fmaf(xv.y, w.w, acc[i * 8 + 7]);
            }
        }
    }

    // --- div partials: 384 threads = 128 positions x 3 c-blocks ---
    {
        const int blk = tid / NOUT;            // 0..2
        const int p   = tid - blk * NOUT;      // 0..127
        const int tx  = p & 15;
        const int ty  = p >> 4;
        const int q0  = (ty + 1) * HX + (tx + 1);
        const int c_lo = (blk == 0) ? 0 : (blk == 1 ? 22 : 43);
        const int c_hi = (blk == 0) ? 22 : (blk == 1 ? 43 : 64);
        float dv = 0.0f;
        for (int c = c_lo; c < c_hi; c++) {
            const float* xc = xs + c * NPOS;
            float cen = xc[q0];
            float d;
            d = xc[q0 - HX - 1] - cen; dv = fmaf(d, d, dv);
            d = xc[q0 - HX    ] - cen; dv = fmaf(d, d, dv);
            d = xc[q0 - HX + 1] - cen; dv = fmaf(d, d, dv);
            d = xc[q0 - 1     ] - cen; dv = fmaf(d, d, dv);
            d = xc[q0 + 1     ] - cen; dv = fmaf(d, d, dv);
            d = xc[q0 + HX - 1] - cen; dv = fmaf(d, d, dv);
            d = xc[q0 + HX    ] - cen; dv = fmaf(d, d, dv);
            d = xc[q0 + HX + 1] - cen; dv = fmaf(d, d, dv);
        }
        dsum[tid] = dv;
    }
    __syncthreads();   // xs reads (GEMM+div) done; dsum visible

    // --- write z halo into xs region ---
    if (active) {
        float* zp = xs + 2 * pp;
#pragma unroll
        for (int i = 0; i < 16; i++) {
            int o = oq * 16 + i;
            *reinterpret_cast<float2*>(zp + o * NPOS) =
                make_float2(acc[i * 2 + 0], acc[i * 2 + 1]);
        }
    }

    // --- combine div partials -> mask ---
    if (tid < NOUT) {
        float dv = dsum[tid] + dsum[tid + NOUT] + dsum[tid + 2 * NOUT];
        float t  = (dv - threshold[0]) * scale[0];
        float sg = 1.0f / (1.0f + expf(-t));
        msk[tid] = (sg > 0.5f) ? 1.0f : 0.0f;
    }
    __syncthreads();

    // --- periphery conv + masked select ---
    const float pr0 = periphery[0], pr1 = periphery[1], pr2 = periphery[2],
                pr3 = periphery[3], pr4 = periphery[4], pr5 = periphery[5],
                pr6 = periphery[6], pr7 = periphery[7];
    float* ob = out + (size_t)b * OO * HWSZ;
    const float* zs = xs;

    for (int i = tid; i < OO * NOUT; i += NTHR) {   // ~21 iters
        int o  = i >> 7;
        int p  = i & 127;
        int tx = p & 15;
        int ty = p >> 4;
        int q0 = (ty + 1) * HX + (tx + 1);
        const float* zo = zs + o * NPOS;
        float cen = zo[q0];
        float a;
        a = pr0 * zo[q0 - HX - 1];
        a = fmaf(pr1, zo[q0 - HX    ], a);
        a = fmaf(pr2, zo[q0 - HX + 1], a);
        a = fmaf(pr3, zo[q0 - 1     ], a);
        a = fmaf(pr4, zo[q0 + 1     ], a);
        a = fmaf(pr5, zo[q0 + HX - 1], a);
        a = fmaf(pr6, zo[q0 + HX    ], a);
        a = fmaf(pr7, zo[q0 + HX + 1], a);
        float r = (msk[p] > 0.5f) ? a : cen;
        __stcg(&ob[(size_t)o * HWSZ + (size_t)(by0 + ty) * WW + (bx0 + tx)], r);
    }
}

extern "C" void kernel_launch(void* const* d_in, const int* in_sizes, int n_in,
                              void* d_out, int out_size) {
    const float* x    = (const float*)d_in[0];
    const float* core = (const float*)d_in[1];
    const float* peri = (const float*)d_in[2];
    const float* thr  = (const float*)d_in[3];
    const float* scl  = (const float*)d_in[4];
    float* out = (float*)d_out;

    const int smem = SMEM_FLOATS * sizeof(float);   // 64,512 B
    cudaFuncSetAttribute(spconv_fused2_kernel,
                         cudaFuncAttributeMaxDynamicSharedMemorySize, smem);

    dim3 grid(WW / TX, HH / TY, BB);   // (8, 16, 8) = 1024 CTAs
    spconv_fused2_kernel<<<grid, NTHR, smem>>>(x, core, peri, thr, scl, out);
}

// round 8
// speedup vs baseline: 1.4225x; 1.0052x over previous
#include <cuda_runtime.h>
#include <math.h>

#define BB 8
#define CC 64
#define OO 64
#define HH 128
#define WW 128
#define HWSZ (HH * WW)

#define TX 16
#define TY 8
#define NOUT (TX * TY)        // 128 outputs per CTA
#define HX 18
#define HY 10
#define NPOS (HX * HY)        // 180 real halo positions
#define NPOSP 192             // padded to 48 quads
#define NTHR 384              // 48 quads * 8 o-groups = 384 slots

// smem (floats):
//   ws   [0, 4096)                W^T [c][o]
//   xs   [4096, 4096+12288)       x halo [c][192]; reused as z halo [o][192]
//   dsum [16384, 16768)           384 div partials
//   msk  [16768, 16896)           128 mask flags
#define WS_OFF 0
#define XS_OFF 4096
#define DS_OFF (XS_OFF + CC * NPOSP)
#define MK_OFF (DS_OFF + NTHR)
#define SMEM_FLOATS (MK_OFF + NOUT)   // 16896 floats = 67,584 B

__global__ __launch_bounds__(NTHR, 2)
void spconv_fused3_kernel(const float* __restrict__ x,
                          const float* __restrict__ core,
                          const float* __restrict__ periphery,
                          const float* __restrict__ threshold,
                          const float* __restrict__ scale,
                          float* __restrict__ out) {
    extern __shared__ float smem[];
    float* ws   = smem + WS_OFF;
    float* xs   = smem + XS_OFF;
    float* dsum = smem + DS_OFF;
    float* msk  = smem + MK_OFF;

    const int tid = threadIdx.x;
    const int b   = blockIdx.z;
    const int bx0 = blockIdx.x * TX;
    const int by0 = blockIdx.y * TY;

    // --- stage W transposed: ws[c][o] = core[o][c] ---
    for (int i = tid; i < OO * CC; i += NTHR) {
        int o = i >> 6, c = i & 63;
        ws[c * 64 + o] = core[i];
    }

    // --- zero pad columns 180..191 ---
    for (int i = tid; i < CC * (NPOSP - NPOS); i += NTHR) {   // 768 entries, 2 iters
        int c = i / (NPOSP - NPOS);
        int p = NPOS + (i - c * (NPOSP - NPOS));
        xs[c * NPOSP + p] = 0.0f;
    }

    // --- stage x halo tile (zero padded), [c][192] ---
    const float* xb = x + (size_t)b * CC * HWSZ;
    for (int i = tid; i < CC * NPOS; i += NTHR) {   // 30 iters
        int c  = i / NPOS;
        int p  = i - c * NPOS;
        int iy = p / HX;
        int ix = p - iy * HX;
        int gy = by0 + iy - 1;
        int gx = bx0 + ix - 1;
        bool inb = ((unsigned)gy < HH) && ((unsigned)gx < WW);
        xs[c * NPOSP + p] = inb ? xb[(size_t)c * HWSZ + gy * WW + gx] : 0.0f;
    }
    __syncthreads();

    // --- GEMM: slot = (o-group of 8, position-quad); 32 accs/thread ---
    float acc[32];
#pragma unroll
    for (int i = 0; i < 32; i++) acc[i] = 0.0f;

    const int og = tid / 48;           // 0..7
    const int q  = tid - og * 48;      // 0..47

    {
        const float* xquad = xs + 4 * q;
        const float* wg    = ws + og * 8;
#pragma unroll 2
        for (int c = 0; c < CC; c++) {
            float4 xv = *reinterpret_cast<const float4*>(xquad + c * NPOSP);
            const float4* w4 = reinterpret_cast<const float4*>(wg + c * 64);
            float4 wa = w4[0];
            float4 wb = w4[1];
#pragma unroll
            for (int pos = 0; pos < 4; pos++) {
                float xp = (pos == 0) ? xv.x : (pos == 1) ? xv.y
                         : (pos == 2) ? xv.z : xv.w;
                acc[0 * 4 + pos] = fmaf(xp, wa.x, acc[0 * 4 + pos]);
                acc[1 * 4 + pos] = fmaf(xp, wa.y, acc[1 * 4 + pos]);
                acc[2 * 4 + pos] = fmaf(xp, wa.z, acc[2 * 4 + pos]);
                acc[3 * 4 + pos] = fmaf(xp, wa.w, acc[3 * 4 + pos]);
                acc[4 * 4 + pos] = fmaf(xp, wb.x, acc[4 * 4 + pos]);
                acc[5 * 4 + pos] = fmaf(xp, wb.y, acc[5 * 4 + pos]);
                acc[6 * 4 + pos] = fmaf(xp, wb.z, acc[6 * 4 + pos]);
                acc[7 * 4 + pos] = fmaf(xp, wb.w, acc[7 * 4 + pos]);
            }
        }
    }

    // --- div partials: 384 threads = 128 positions x 3 c-blocks ---
    {
        const int blk = tid / NOUT;            // 0..2
        const int p   = tid - blk * NOUT;      // 0..127
        const int tx  = p & 15;
        const int ty  = p >> 4;
        const int q0  = (ty + 1) * HX + (tx + 1);
        const int c_lo = (blk == 0) ? 0 : (blk == 1 ? 22 : 43);
        const int c_hi = (blk == 0) ? 22 : (blk == 1 ? 43 : 64);
        float dv = 0.0f;
        for (int c = c_lo; c < c_hi; c++) {
            const float* xc = xs + c * NPOSP;
            float cen = xc[q0];
            float d;
            d = xc[q0 - HX - 1] - cen; dv = fmaf(d, d, dv);
            d = xc[q0 - HX    ] - cen; dv = fmaf(d, d, dv);
            d = xc[q0 - HX + 1] - cen; dv = fmaf(d, d, dv);
            d = xc[q0 - 1     ] - cen; dv = fmaf(d, d, dv);
            d = xc[q0 + 1     ] - cen; dv = fmaf(d, d, dv);
            d = xc[q0 + HX - 1] - cen; dv = fmaf(d, d, dv);
            d = xc[q0 + HX    ] - cen; dv = fmaf(d, d, dv);
            d = xc[q0 + HX + 1] - cen; dv = fmaf(d, d, dv);
        }
        dsum[tid] = dv;
    }
    __syncthreads();   // all xs reads done; dsum visible

    // --- write z halo into xs region: 8 x STS.128 ---
    {
        float* zq = xs + 4 * q;
#pragma unroll
        for (int i = 0; i < 8; i++) {
            int o = og * 8 + i;
            *reinterpret_cast<float4*>(zq + o * NPOSP) =
                make_float4(acc[i * 4 + 0], acc[i * 4 + 1],
                            acc[i * 4 + 2], acc[i * 4 + 3]);
        }
    }

    // --- combine div partials -> mask ---
    if (tid < NOUT) {
        float dv = dsum[tid] + dsum[tid + NOUT] + dsum[tid + 2 * NOUT];
        float t  = (dv - threshold[0]) * scale[0];
        float sg = 1.0f / (1.0f + expf(-t));
        msk[tid] = (sg > 0.5f) ? 1.0f : 0.0f;
    }
    __syncthreads();

    // --- periphery conv + masked select ---
    const float pr0 = periphery[0], pr1 = periphery[1], pr2 = periphery[2],
                pr3 = periphery[3], pr4 = periphery[4], pr5 = periphery[5],
                pr6 = periphery[6], pr7 = periphery[7];
    float* ob = out + (size_t)b * OO * HWSZ;
    const float* zs = xs;

    for (int i = tid; i < OO * NOUT; i += NTHR) {   // ~21 iters
        int o  = i >> 7;
        int p  = i & 127;
        int tx = p & 15;
        int ty = p >> 4;
        int q0 = (ty + 1) * HX + (tx + 1);
        const float* zo = zs + o * NPOSP;
        float cen = zo[q0];
        float a;
        a = pr0 * zo[q0 - HX - 1];
        a = fmaf(pr1, zo[q0 - HX    ], a);
        a = fmaf(pr2, zo[q0 - HX + 1], a);
        a = fmaf(pr3, zo[q0 - 1     ], a);
        a = fmaf(pr4, zo[q0 + 1     ], a);
        a = fmaf(pr5, zo[q0 + HX - 1], a);
        a = fmaf(pr6, zo[q0 + HX    ], a);
        a = fmaf(pr7, zo[q0 + HX + 1], a);
        float r = (msk[p] > 0.5f) ? a : cen;
        __stcg(&ob[(size_t)o * HWSZ + (size_t)(by0 + ty) * WW + (bx0 + tx)], r);
    }
}

extern "C" void kernel_launch(void* const* d_in, const int* in_sizes, int n_in,
                              void* d_out, int out_size) {
    const float* x    = (const float*)d_in[0];
    const float* core = (const float*)d_in[1];
    const float* peri = (const float*)d_in[2];
    const float* thr  = (const float*)d_in[3];
    const float* scl  = (const float*)d_in[4];
    float* out = (float*)d_out;

    const int smem = SMEM_FLOATS * sizeof(float);   // 67,584 B
    cudaFuncSetAttribute(spconv_fused3_kernel,
                         cudaFuncAttributeMaxDynamicSharedMemorySize, smem);

    dim3 grid(WW / TX, HH / TY, BB);   // (8, 16, 8) = 1024 CTAs
    spconv_fused3_kernel<<<grid, NTHR, smem>>>(x, core, peri, thr, scl, out);
}

// round 9
// speedup vs baseline: 1.9424x; 1.3654x over previous
#include <cuda_runtime.h>
#include <cuda_bf16.h>
#include <math.h>
#include <stdint.h>

#define BB 8
#define CC 64
#define OO 64
#define HH 128
#define WW 128
#define HWSZ (HH * WW)

#define TX 16
#define TY 8
#define NOUT 128            // outputs per CTA
#define HX 18
#define HY 10
#define NPOS 180            // real halo positions
#define MPOS 192            // padded to 12 m-tiles of 16
#define NTHR 384            // 12 warps
#define LDP 68              // words per P row (pad for banks)
#define LDB 68
#define LDZ 196             // floats per zs row (pad for writeback banks)

// smem byte offsets
#define P_B   0                         // packed A: [192 pos][68 w] uint32 (hi|lo<<16)
#define B1_B  (P_B + MPOS * LDP * 4)    // 52224: (Wh,Wh) [64 o][68 w]
#define B2_B  (B1_B + OO * LDB * 4)     // 69632: (Wl,0)  [64 o][68 w]
#define DS_B  (B2_B + OO * LDB * 4)     // 87040: div partials [384]
#define MK_B  (DS_B + NTHR * 4)         // 88576: mask [128]
#define SMEM_BYTES (MK_B + NOUT * 4)    // 89088

__device__ __forceinline__ float bf_hi(uint32_t w) {
    return __uint_as_float(w << 16);
}

__device__ __forceinline__ void mma_bf16(float* c, uint32_t a0, uint32_t a1,
                                         uint32_t a2, uint32_t a3,
                                         uint32_t b0, uint32_t b1) {
    asm volatile(
        "mma.sync.aligned.m16n8k16.row.col.f32.bf16.bf16.f32 "
        "{%0,%1,%2,%3}, {%4,%5,%6,%7}, {%8,%9}, {%0,%1,%2,%3};"
        : "+f"(c[0]), "+f"(c[1]), "+f"(c[2]), "+f"(c[3])
        : "r"(a0), "r"(a1), "r"(a2), "r"(a3), "r"(b0), "r"(b1));
}

__global__ __launch_bounds__(NTHR, 2)
void spconv_mma_kernel(const float* __restrict__ x,
                       const float* __restrict__ core,
                       const float* __restrict__ periphery,
                       const float* __restrict__ threshold,
                       const float* __restrict__ scale,
                       float* __restrict__ out) {
    extern __shared__ char smem[];
    uint32_t* Pw  = (uint32_t*)(smem + P_B);
    uint32_t* B1w = (uint32_t*)(smem + B1_B);
    uint32_t* B2w = (uint32_t*)(smem + B2_B);
    float* dsum   = (float*)(smem + DS_B);
    float* msk    = (float*)(smem + MK_B);

    const int tid = threadIdx.x;
    const int wid = tid >> 5;
    const int lid = tid & 31;
    const int b   = blockIdx.z;
    const int bx0 = blockIdx.x * TX;
    const int by0 = blockIdx.y * TY;

    // --- stage W: B1 = (Wh|Wh), B2 = (Wl|0)  (core is [o][c] row-major) ---
    for (int i = tid; i < OO * CC; i += NTHR) {
        int o = i >> 6, c = i & 63;
        float v = core[i];
        __nv_bfloat16 h = __float2bfloat16(v);
        uint32_t hb = (uint32_t)__bfloat16_as_ushort(h);
        __nv_bfloat16 l = __float2bfloat16(v - __bfloat162float(h));
        uint32_t lb = (uint32_t)__bfloat16_as_ushort(l);
        B1w[o * LDB + c] = hb | (hb << 16);
        B2w[o * LDB + c] = lb;                 // low = Wl, high = 0
    }

    // --- zero pad rows 180..191 of P ---
    for (int i = tid; i < (MPOS - NPOS) * CC; i += NTHR) {   // 768, 2 iters
        int p = NPOS + (i >> 6);
        int c = i & 63;
        Pw[p * LDP + c] = 0u;
    }

    // --- stage x halo -> packed P[pos][c] = (hi | lo<<16) ---
    const float* xb = x + (size_t)b * CC * HWSZ;
    for (int i = tid; i < CC * NPOS; i += NTHR) {   // 30 iters exact
        int c  = i / NPOS;
        int p  = i - c * NPOS;
        int iy = p / HX;
        int ix = p - iy * HX;
        int gy = by0 + iy - 1;
        int gx = bx0 + ix - 1;
        bool inb = ((unsigned)gy < HH) && ((unsigned)gx < WW);
        float v = inb ? xb[(size_t)c * HWSZ + gy * WW + gx] : 0.0f;
        __nv_bfloat16 h = __float2bfloat16(v);
        uint32_t hb = (uint32_t)__bfloat16_as_ushort(h);
        __nv_bfloat16 l = __float2bfloat16(v - __bfloat162float(h));
        uint32_t lb = (uint32_t)__bfloat16_as_ushort(l);
        Pw[p * LDP + c] = hb | (lb << 16);
    }
    __syncthreads();

    // --- tensor GEMM: warp = m-tile (16 pos), loop 8 k-tiles x 8 n-tiles ---
    float Cacc[8][4];
#pragma unroll
    for (int nt = 0; nt < 8; nt++)
#pragma unroll
        for (int j = 0; j < 4; j++) Cacc[nt][j] = 0.0f;

    const int g = lid >> 2;       // 0..7
    const int t = lid & 3;        // 0..3
    {
        const int row0 = wid * 16 + g;
        const int row8 = row0 + 8;
#pragma unroll
        for (int kt = 0; kt < 8; kt++) {
            const int kb = kt * 8;
            uint32_t a0 = Pw[row0 * LDP + kb + t];
            uint32_t a1 = Pw[row8 * LDP + kb + t];
            uint32_t a2 = Pw[row0 * LDP + kb + t + 4];
            uint32_t a3 = Pw[row8 * LDP + kb + t + 4];
#pragma unroll
            for (int nt = 0; nt < 8; nt++) {
                const int brow = nt * 8 + g;
                uint32_t b0 = B1w[brow * LDB + kb + t];
                uint32_t b1 = B1w[brow * LDB + kb + t + 4];
                mma_bf16(Cacc[nt], a0, a1, a2, a3, b0, b1);
                uint32_t d0 = B2w[brow * LDB + kb + t];
                uint32_t d1 = B2w[brow * LDB + kb + t + 4];
                mma_bf16(Cacc[nt], a0, a1, a2, a3, d0, d1);
            }
        }
    }

    // --- div from P (hi halves): 3 c-blocks x 128 positions ---
    {
        const int p   = tid & 127;
        const int blk = tid >> 7;                  // 0..2
        const int tx  = p & 15;
        const int ty  = p >> 4;
        const int q0  = (ty + 1) * HX + (tx + 1);
        const int cw0 = (blk == 0) ? 0 : (blk == 1 ? 6 : 11);
        const int cw1 = (blk == 0) ? 6 : (blk == 1 ? 11 : 16);
        float dv = 0.0f;
        for (int cw = cw0; cw < cw1; cw++) {
            uint4 cc = *(const uint4*)(Pw + q0 * LDP + cw * 4);
            float c0 = bf_hi(cc.x), c1 = bf_hi(cc.y),
                  c2 = bf_hi(cc.z), c3 = bf_hi(cc.w);
            const int offs[8] = {-HX - 1, -HX, -HX + 1, -1, 1, HX - 1, HX, HX + 1};
#pragma unroll
            for (int k = 0; k < 8; k++) {
                uint4 tt = *(const uint4*)(Pw + (q0 + offs[k]) * LDP + cw * 4);
                float d;
                d = bf_hi(tt.x) - c0; dv = fmaf(d, d, dv);
                d = bf_hi(tt.y) - c1; dv = fmaf(d, d, dv);
                d = bf_hi(tt.z) - c2; dv = fmaf(d, d, dv);
                d = bf_hi(tt.w) - c3; dv = fmaf(d, d, dv);
            }
        }
        dsum[tid] = dv;
    }
    __syncthreads();   // all P reads done

    // --- write z (fp32) over the P region: zs[o][LDZ] ---
    float* zs = (float*)smem;
    {
        const int pos0 = wid * 16 + g;
        const int pos8 = pos0 + 8;
#pragma unroll
        for (int nt = 0; nt < 8; nt++) {
            const int o0 = nt * 8 + 2 * t;
            zs[o0 * LDZ + pos0]       = Cacc[nt][0];
            zs[(o0 + 1) * LDZ + pos0] = Cacc[nt][1];
            zs[o0 * LDZ + pos8]       = Cacc[nt][2];
            zs[(o0 + 1) * LDZ + pos8] = Cacc[nt][3];
        }
    }

    // --- mask ---
    if (tid < NOUT) {
        float dv = dsum[tid] + dsum[tid + NOUT] + dsum[tid + 2 * NOUT];
        float tt = (dv - threshold[0]) * scale[0];
        float sg = 1.0f / (1.0f + expf(-tt));
        msk[tid] = (sg > 0.5f) ? 1.0f : 0.0f;
    }
    __syncthreads();

    // --- periphery conv + masked select ---
    const float pr0 = periphery[0], pr1 = periphery[1], pr2 = periphery[2],
                pr3 = periphery[3], pr4 = periphery[4], pr5 = periphery[5],
                pr6 = periphery[6], pr7 = periphery[7];
    float* ob = out + (size_t)b * OO * HWSZ;

    for (int i = tid; i < OO * NOUT; i += NTHR) {
        int o  = i >> 7;
        int p  = i & 127;
        int tx = p & 15;
        int ty = p >> 4;
        int q0 = (ty + 1) * HX + (tx + 1);
        const float* zo = zs + o * LDZ;
        float cen = zo[q0];
        float a;
        a = pr0 * zo[q0 - HX - 1];
        a = fmaf(pr1, zo[q0 - HX    ], a);
        a = fmaf(pr2, zo[q0 - HX + 1], a);
        a = fmaf(pr3, zo[q0 - 1     ], a);
        a = fmaf(pr4, zo[q0 + 1     ], a);
        a = fmaf(pr5, zo[q0 + HX - 1], a);
        a = fmaf(pr6, zo[q0 + HX    ], a);
        a = fmaf(pr7, zo[q0 + HX + 1], a);
        float r = (msk[p] > 0.5f) ? a : cen;
        __stcg(&ob[(size_t)o * HWSZ + (size_t)(by0 + ty) * WW + (bx0 + tx)], r);
    }
}

extern "C" void kernel_launch(void* const* d_in, const int* in_sizes, int n_in,
                              void* d_out, int out_size) {
    const float* x    = (const float*)d_in[0];
    const float* core = (const float*)d_in[1];
    const float* peri = (const float*)d_in[2];
    const float* thr  = (const float*)d_in[3];
    const float* scl  = (const float*)d_in[4];
    float* out = (float*)d_out;

    cudaFuncSetAttribute(spconv_mma_kernel,
                         cudaFuncAttributeMaxDynamicSharedMemorySize, SMEM_BYTES);

    dim3 grid(WW / TX, HH / TY, BB);   // 1024 CTAs
    spconv_mma_kernel<<<grid, NTHR, SMEM_BYTES>>>(x, core, peri, thr, scl, out);
}

// round 11
// speedup vs baseline: 2.0573x; 1.0592x over previous
#include <cuda_runtime.h>
#include <cuda_bf16.h>
#include <math.h>
#include <stdint.h>

#define BB 8
#define CC 64
#define OO 64
#define HH 128
#define WW 128
#define HWSZ (HH * WW)

#define TX 16
#define TY 8
#define NOUT 128            // outputs per CTA
#define HX 18
#define HY 10
#define NPOS 180            // real halo positions
#define MPOS 192            // padded to 12 m-tiles of 16
#define NTHR 384            // 12 warps
#define LDP 68              // words per P row
#define LDB 68
#define LDZ 196             // floats per zs row

// smem byte offsets
#define P_B   0                         // packed A: [192 pos][68 w] (hi|lo<<16)
#define B1_B  (P_B + MPOS * LDP * 4)    // 52224: (Wh|Wh) [64 o][68 w]
#define B2_B  (B1_B + OO * LDB * 4)     // 69632: (Wl|Wl)
#define DS_B  (B2_B + OO * LDB * 4)     // 87040: div partials [384]
#define MK_B  (DS_B + NTHR * 4)         // 88576: mask [128]
#define SMEM_BYTES (MK_B + NOUT * 4)    // 89088

__device__ __forceinline__ float bf_hi(uint32_t w) {
    return __uint_as_float(w << 16);
}

__device__ __forceinline__ uint32_t smem_u32(const void* p) {
    uint32_t a;
    asm("{ .reg .u64 t; cvta.to.shared.u64 t, %1; cvt.u32.u64 %0, t; }"
        : "=r"(a) : "l"(p));
    return a;
}

__device__ __forceinline__ void ldsm4(uint32_t& r0, uint32_t& r1,
                                      uint32_t& r2, uint32_t& r3,
                                      uint32_t addr) {
    asm volatile("ldmatrix.sync.aligned.m8n8.x4.shared.b16 {%0,%1,%2,%3}, [%4];"
                 : "=r"(r0), "=r"(r1), "=r"(r2), "=r"(r3) : "r"(addr));
}

__device__ __forceinline__ void mma_bf16(float* c, uint32_t a0, uint32_t a1,
                                         uint32_t a2, uint32_t a3,
                                         uint32_t b0, uint32_t b1) {
    asm volatile(
        "mma.sync.aligned.m16n8k16.row.col.f32.bf16.bf16.f32 "
        "{%0,%1,%2,%3}, {%4,%5,%6,%7}, {%8,%9}, {%0,%1,%2,%3};"
        : "+f"(c[0]), "+f"(c[1]), "+f"(c[2]), "+f"(c[3])
        : "r"(a0), "r"(a1), "r"(a2), "r"(a3), "r"(b0), "r"(b1));
}

__global__ __launch_bounds__(NTHR, 2)
void spconv_mma2_kernel(const float* __restrict__ x,
                        const float* __restrict__ core,
                        const float* __restrict__ periphery,
                        const float* __restrict__ threshold,
                        const float* __restrict__ scale,
                        float* __restrict__ out) {
    extern __shared__ char smem[];
    uint32_t* Pw  = (uint32_t*)(smem + P_B);
    uint32_t* B1w = (uint32_t*)(smem + B1_B);
    uint32_t* B2w = (uint32_t*)(smem + B2_B);
    float* dsum   = (float*)(smem + DS_B);
    float* msk    = (float*)(smem + MK_B);

    const int tid = threadIdx.x;
    const int wid = tid >> 5;
    const int lid = tid & 31;
    const int b   = blockIdx.z;
    const int bx0 = blockIdx.x * TX;
    const int by0 = blockIdx.y * TY;

    // --- stage W: B1 = (Wh|Wh), B2 = (Wl|Wl) ---
    for (int i = tid; i < OO * CC; i += NTHR) {
        int o = i >> 6, c = i & 63;
        float v = core[i];
        __nv_bfloat16 h = __float2bfloat16(v);
        uint32_t hb = (uint32_t)__bfloat16_as_ushort(h);
        __nv_bfloat16 l = __float2bfloat16(v - __bfloat162float(h));
        uint32_t lb = (uint32_t)__bfloat16_as_ushort(l);
        B1w[o * LDB + c] = hb | (hb << 16);
        B2w[o * LDB + c] = lb | (lb << 16);
    }

    // --- zero pad rows 180..191 of P ---
    for (int i = tid; i < (MPOS - NPOS) * CC; i += NTHR) {
        int p = NPOS + (i >> 6);
        int c = i & 63;
        Pw[p * LDP + c] = 0u;
    }

    // --- stage x halo -> packed P[pos][c] = (hi | lo<<16) ---
    const float* xb = x + (size_t)b * CC * HWSZ;
    for (int i = tid; i < CC * NPOS; i += NTHR) {
        int c  = i / NPOS;
        int p  = i - c * NPOS;
        int iy = p / HX;
        int ix = p - iy * HX;
        int gy = by0 + iy - 1;
        int gx = bx0 + ix - 1;
        bool inb = ((unsigned)gy < HH) && ((unsigned)gx < WW);
        float v = inb ? xb[(size_t)c * HWSZ + gy * WW + gx] : 0.0f;
        __nv_bfloat16 h = __float2bfloat16(v);
        uint32_t hb = (uint32_t)__bfloat16_as_ushort(h);
        __nv_bfloat16 l = __float2bfloat16(v - __bfloat162float(h));
        uint32_t lb = (uint32_t)__bfloat16_as_ushort(l);
        Pw[p * LDP + c] = hb | (lb << 16);
    }
    __syncthreads();

    // --- tensor GEMM: warp = 2 m-tiles x 4 n-tiles ---
    const int mp = wid >> 1;            // 0..5  -> rows mp*32 .. mp*32+31
    const int nh = wid & 1;             // 0..1  -> o cols nh*32 .. nh*32+31
    const int mbase = mp * 32;

    float Cacc[2][4][4];
#pragma unroll
    for (int mt = 0; mt < 2; mt++)
#pragma unroll
        for (int j = 0; j < 4; j++)
#pragma unroll
            for (int v = 0; v < 4; v++) Cacc[mt][j][v] = 0.0f;

    const uint32_t sb = smem_u32(smem);
    // A lane ptrs: lanes 0-7 rows 0-7@col0, 8-15 rows 8-15@col0,
    //              16-23 rows 0-7@col4, 24-31 rows 8-15@col4
    const int arow = mbase + (lid & 15);
    const int acol = (lid >> 4) * 4;
    uint32_t aptr0 = sb + P_B + (uint32_t)(arow * LDP + acol) * 4;
    uint32_t aptr1 = aptr0 + 16 * LDP * 4;
    // B lane ptrs: lanes 0-15 -> B1 (cols 0 / 4), lanes 16-31 -> B2
    const int brow = nh * 32 + (lid & 7);
    const int bcol = ((lid >> 3) & 1) * 4;
    uint32_t bptr = sb + ((lid >> 4) ? B2_B : B1_B)
                  + (uint32_t)(brow * LDB + bcol) * 4;

#pragma unroll
    for (int kt = 0; kt < 8; kt++) {
        uint32_t a0, a1, a2, a3, a4, a5, a6, a7;
        ldsm4(a0, a1, a2, a3, aptr0);
        ldsm4(a4, a5, a6, a7, aptr1);
        uint32_t bp = bptr;
#pragma unroll
        for (int j = 0; j < 4; j++) {
            uint32_t b0, b1, d0, d1;
            ldsm4(b0, b1, d0, d1, bp);
            mma_bf16(Cacc[0][j], a0, a1, a2, a3, b0, b1);
            mma_bf16(Cacc[0][j], a0, a1, a2, a3, d0, d1);
            mma_bf16(Cacc[1][j], a4, a5, a6, a7, b0, b1);
            mma_bf16(Cacc[1][j], a4, a5, a6, a7, d0, d1);
            bp += 8 * LDB * 4;
        }
        aptr0 += 32; aptr1 += 32; bptr += 32;
    }

    // --- div from P (hi halves): 3 c-blocks x 128 positions ---
    {
        const int p   = tid & 127;
        const int blk = tid >> 7;
        const int tx  = p & 15;
        const int ty  = p >> 4;
        const int q0  = (ty + 1) * HX + (tx + 1);
        const int cw0 = (blk == 0) ? 0 : (blk == 1 ? 6 : 11);
        const int cw1 = (blk == 0) ? 6 : (blk == 1 ? 11 : 16);
        float dv = 0.0f;
        for (int cw = cw0; cw < cw1; cw++) {
            uint4 cc = *(const uint4*)(Pw + q0 * LDP + cw * 4);
            float c0 = bf_hi(cc.x), c1 = bf_hi(cc.y),
                  c2 = bf_hi(cc.z), c3 = bf_hi(cc.w);
            const int offs[8] = {-HX - 1, -HX, -HX + 1, -1, 1, HX - 1, HX, HX + 1};
#pragma unroll
            for (int k = 0; k < 8; k++) {
                uint4 tt = *(const uint4*)(Pw + (q0 + offs[k]) * LDP + cw * 4);
                float d;
                d = bf_hi(tt.x) - c0; dv = fmaf(d, d, dv);
                d = bf_hi(tt.y) - c1; dv = fmaf(d, d, dv);
                d = bf_hi(tt.z) - c2; dv = fmaf(d, d, dv);
                d = bf_hi(tt.w) - c3; dv = fmaf(d, d, dv);
            }
        }
        dsum[tid] = dv;
    }
    __syncthreads();   // all P reads done

    // --- write z (fp32) over the P region: zs[o][LDZ] ---
    float* zs = (float*)smem;
    {
        const int g = lid >> 2;
        const int t = lid & 3;
#pragma unroll
        for (int mt = 0; mt < 2; mt++) {
            const int pos = mbase + mt * 16 + g;
#pragma unroll
            for (int j = 0; j < 4; j++) {
                const int o0 = nh * 32 + j * 8 + 2 * t;
                zs[o0 * LDZ + pos]           = Cacc[mt][j][0];
                zs[(o0 + 1) * LDZ + pos]     = Cacc[mt][j][1];
                zs[o0 * LDZ + pos + 8]       = Cacc[mt][j][2];
                zs[(o0 + 1) * LDZ + pos + 8] = Cacc[mt][j][3];
            }
        }
    }

    // --- mask ---
    if (tid < NOUT) {
        float dv = dsum[tid] + dsum[tid + NOUT] + dsum[tid + 2 * NOUT];
        float tt = (dv - threshold[0]) * scale[0];
        float sg = 1.0f / (1.0f + expf(-tt));
        msk[tid] = (sg > 0.5f) ? 1.0f : 0.0f;
    }
    __syncthreads();

    // --- periphery conv + masked select ---
    const float pr0 = periphery[0], pr1 = periphery[1], pr2 = periphery[2],
                pr3 = periphery[3], pr4 = periphery[4], pr5 = periphery[5],
                pr6 = periphery[6], pr7 = periphery[7];
    float* ob = out + (size_t)b * OO * HWSZ;

    for (int i = tid; i < OO * NOUT; i += NTHR) {
        int o  = i >> 7;
        int p  = i & 127;
        int tx = p & 15;
        int ty = p >> 4;
        int q0 = (ty + 1) * HX + (tx + 1);
        const float* zo = zs + o * LDZ;
        float cen = zo[q0];
        float a;
        a = pr0 * zo[q0 - HX - 1];
        a = fmaf(pr1, zo[q0 - HX    ], a);
        a = fmaf(pr2, zo[q0 - HX + 1], a);
        a = fmaf(pr3, zo[q0 - 1     ], a);
        a = fmaf(pr4, zo[q0 + 1     ], a);
        a = fmaf(pr5, zo[q0 + HX - 1], a);
        a = fmaf(pr6, zo[q0 + HX    ], a);
        a = fmaf(pr7, zo[q0 + HX + 1], a);
        float r = (msk[p] > 0.5f) ? a : cen;
        __stcg(&ob[(size_t)o * HWSZ + (size_t)(by0 + ty) * WW + (bx0 + tx)], r);
    }
}

extern "C" void kernel_launch(void* const* d_in, const int* in_sizes, int n_in,
                              void* d_out, int out_size) {
    const float* x    = (const float*)d_in[0];
    const float* core = (const float*)d_in[1];
    const float* peri = (const float*)d_in[2];
    const float* thr  = (const float*)d_in[3];
    const float* scl  = (const float*)d_in[4];
    float* out = (float*)d_out;

    cudaFuncSetAttribute(spconv_mma2_kernel,
                         cudaFuncAttributeMaxDynamicSharedMemorySize, SMEM_BYTES);

    dim3 grid(WW / TX, HH / TY, BB);   // 1024 CTAs
    spconv_mma2_kernel<<<grid, NTHR, SMEM_BYTES>>>(x, core, peri, thr, scl, out);
}

// round 13
// speedup vs baseline: 2.3397x; 1.1373x over previous
#include <cuda_runtime.h>
#include <cuda_bf16.h>
#include <math.h>
#include <stdint.h>

#define BB 8
#define CC 64
#define OO 64
#define HH 128
#define WW 128
#define HWSZ (HH * WW)

#define TX 16
#define TY 8
#define NOUT 128            // outputs per CTA
#define HX 18
#define HY 10
#define NPOS 180            // real halo positions
#define MPOS 192            // padded to 12 m-tiles of 16
#define NTHR 384            // 12 warps
#define LDP 68              // words per P row
#define LDB 68
#define LDZ 196             // floats per zs row

// smem byte offsets
#define P_B   0                         // packed A: [192 pos][68 w] (hi|lo<<16)
#define B1_B  (P_B + MPOS * LDP * 4)    // 52224: (Wh|Wh) [64 o][68 w]
#define B2_B  (B1_B + OO * LDB * 4)     // 69632: (Wl|Wl)
#define DS_B  (B2_B + OO * LDB * 4)     // 87040: div partials [384]
#define MK_B  (DS_B + NTHR * 4)         // 88576: mask [128]
#define SMEM_BYTES (MK_B + NOUT * 4)    // 89088

__device__ __forceinline__ float bf_hi(uint32_t w) {
    return __uint_as_float(w << 16);
}

__device__ __forceinline__ uint32_t smem_u32(const void* p) {
    uint32_t a;
    asm("{ .reg .u64 t; cvta.to.shared.u64 t, %1; cvt.u32.u64 %0, t; }"
        : "=r"(a) : "l"(p));
    return a;
}

__device__ __forceinline__ void ldsm4(uint32_t& r0, uint32_t& r1,
                                      uint32_t& r2, uint32_t& r3,
                                      uint32_t addr) {
    asm volatile("ldmatrix.sync.aligned.m8n8.x4.shared.b16 {%0,%1,%2,%3}, [%4];"
                 : "=r"(r0), "=r"(r1), "=r"(r2), "=r"(r3) : "r"(addr));
}

__device__ __forceinline__ void mma_bf16(float* c, uint32_t a0, uint32_t a1,
                                         uint32_t a2, uint32_t a3,
                                         uint32_t b0, uint32_t b1) {
    asm volatile(
        "mma.sync.aligned.m16n8k16.row.col.f32.bf16.bf16.f32 "
        "{%0,%1,%2,%3}, {%4,%5,%6,%7}, {%8,%9}, {%0,%1,%2,%3};"
        : "+f"(c[0]), "+f"(c[1]), "+f"(c[2]), "+f"(c[3])
        : "r"(a0), "r"(a1), "r"(a2), "r"(a3), "r"(b0), "r"(b1));
}

__global__ __launch_bounds__(NTHR, 2)
void spconv_mma3_kernel(const float* __restrict__ x,
                        const float* __restrict__ core,
                        const float* __restrict__ periphery,
                        const float* __restrict__ threshold,
                        const float* __restrict__ scale,
                        float* __restrict__ out) {
    extern __shared__ char smem[];
    uint32_t* Pw  = (uint32_t*)(smem + P_B);
    uint32_t* B1w = (uint32_t*)(smem + B1_B);
    uint32_t* B2w = (uint32_t*)(smem + B2_B);
    float* dsum   = (float*)(smem + DS_B);
    float* msk    = (float*)(smem + MK_B);

    const int tid = threadIdx.x;
    const int wid = tid >> 5;
    const int lid = tid & 31;
    const int b   = blockIdx.z;
    const int bx0 = blockIdx.x * TX;
    const int by0 = blockIdx.y * TY;

    // --- stage W: B1 = (Wh|Wh), B2 = (Wl|Wl) ---
    for (int i = tid; i < OO * CC; i += NTHR) {
        int o = i >> 6, c = i & 63;
        float v = core[i];
        __nv_bfloat16 h = __float2bfloat16(v);
        uint32_t hb = (uint32_t)__bfloat16_as_ushort(h);
        __nv_bfloat16 l = __float2bfloat16(v - __bfloat162float(h));
        uint32_t lb = (uint32_t)__bfloat16_as_ushort(l);
        B1w[o * LDB + c] = hb | (hb << 16);
        B2w[o * LDB + c] = lb | (lb << 16);
    }

    // --- zero pad rows 180..191 of P ---
    for (int i = tid; i < (MPOS - NPOS) * CC; i += NTHR) {
        int p = NPOS + (i >> 6);
        int c = i & 63;
        Pw[p * LDP + c] = 0u;
    }

    // --- stage x halo -> packed P[pos][c] = (hi | lo<<16) ---
    const float* xb = x + (size_t)b * CC * HWSZ;
    for (int i = tid; i < CC * NPOS; i += NTHR) {
        int c  = i / NPOS;
        int p  = i - c * NPOS;
        int iy = p / HX;
        int ix = p - iy * HX;
        int gy = by0 + iy - 1;
        int gx = bx0 + ix - 1;
        bool inb = ((unsigned)gy < HH) && ((unsigned)gx < WW);
        float v = inb ? xb[(size_t)c * HWSZ + gy * WW + gx] : 0.0f;
        __nv_bfloat16 h = __float2bfloat16(v);
        uint32_t hb = (uint32_t)__bfloat16_as_ushort(h);
        __nv_bfloat16 l = __float2bfloat16(v - __bfloat162float(h));
        uint32_t lb = (uint32_t)__bfloat16_as_ushort(l);
        Pw[p * LDP + c] = hb | (lb << 16);
    }
    __syncthreads();

    // --- tensor GEMM: warp = 2 m-tiles x 4 n-tiles ---
    const int mp = wid >> 1;
    const int nh = wid & 1;
    const int mbase = mp * 32;

    float Cacc[2][4][4];
#pragma unroll
    for (int mt = 0; mt < 2; mt++)
#pragma unroll
        for (int j = 0; j < 4; j++)
#pragma unroll
            for (int v = 0; v < 4; v++) Cacc[mt][j][v] = 0.0f;

    const uint32_t sb = smem_u32(smem);
    const int arow = mbase + (lid & 15);
    const int acol = (lid >> 4) * 4;
    uint32_t aptr0 = sb + P_B + (uint32_t)(arow * LDP + acol) * 4;
    uint32_t aptr1 = aptr0 + 16 * LDP * 4;
    const int brow = nh * 32 + (lid & 7);
    const int bcol = ((lid >> 3) & 1) * 4;
    uint32_t bptr = sb + ((lid >> 4) ? B2_B : B1_B)
                  + (uint32_t)(brow * LDB + bcol) * 4;

#pragma unroll
    for (int kt = 0; kt < 8; kt++) {
        uint32_t a0, a1, a2, a3, a4, a5, a6, a7;
        ldsm4(a0, a1, a2, a3, aptr0);
        ldsm4(a4, a5, a6, a7, aptr1);
        uint32_t bp = bptr;
#pragma unroll
        for (int j = 0; j < 4; j++) {
            uint32_t b0, b1, d0, d1;
            ldsm4(b0, b1, d0, d1, bp);
            mma_bf16(Cacc[0][j], a0, a1, a2, a3, b0, b1);
            mma_bf16(Cacc[0][j], a0, a1, a2, a3, d0, d1);
            mma_bf16(Cacc[1][j], a4, a5, a6, a7, b0, b1);
            mma_bf16(Cacc[1][j], a4, a5, a6, a7, d0, d1);
            bp += 8 * LDB * 4;
        }
        aptr0 += 32; aptr1 += 32; bptr += 32;
    }

    // --- div from P (hi halves): 3 c-blocks x 128 positions ---
    {
        const int p   = tid & 127;
        const int blk = tid >> 7;
        const int tx  = p & 15;
        const int ty  = p >> 4;
        const int q0  = (ty + 1) * HX + (tx + 1);
        const int cw0 = (blk == 0) ? 0 : (blk == 1 ? 6 : 11);
        const int cw1 = (blk == 0) ? 6 : (blk == 1 ? 11 : 16);
        float dv = 0.0f;
        for (int cw = cw0; cw < cw1; cw++) {
            uint4 cc = *(const uint4*)(Pw + q0 * LDP + cw * 4);
            float c0 = bf_hi(cc.x), c1 = bf_hi(cc.y),
                  c2 = bf_hi(cc.z), c3 = bf_hi(cc.w);
            const int offs[8] = {-HX - 1, -HX, -HX + 1, -1, 1, HX - 1, HX, HX + 1};
#pragma unroll
            for (int k = 0; k < 8; k++) {
                uint4 tt = *(const uint4*)(Pw + (q0 + offs[k]) * LDP + cw * 4);
                float d;
                d = bf_hi(tt.x) - c0; dv = fmaf(d, d, dv);
                d = bf_hi(tt.y) - c1; dv = fmaf(d, d, dv);
                d = bf_hi(tt.z) - c2; dv = fmaf(d, d, dv);
                d = bf_hi(tt.w) - c3; dv = fmaf(d, d, dv);
            }
        }
        dsum[tid] = dv;
    }
    __syncthreads();   // all P reads done

    // --- write z (fp32) over the P region: zs[o][LDZ] ---
    float* zs = (float*)smem;
    {
        const int g = lid >> 2;
        const int t = lid & 3;
#pragma unroll
        for (int mt = 0; mt < 2; mt++) {
            const int pos = mbase + mt * 16 + g;
#pragma unroll
            for (int j = 0; j < 4; j++) {
                const int o0 = nh * 32 + j * 8 + 2 * t;
                zs[o0 * LDZ + pos]           = Cacc[mt][j][0];
                zs[(o0 + 1) * LDZ + pos]     = Cacc[mt][j][1];
                zs[o0 * LDZ + pos + 8]       = Cacc[mt][j][2];
                zs[(o0 + 1) * LDZ + pos + 8] = Cacc[mt][j][3];
            }
        }
    }

    // --- mask ---
    if (tid < NOUT) {
        float dv = dsum[tid] + dsum[tid + NOUT] + dsum[tid + 2 * NOUT];
        float tt = (dv - threshold[0]) * scale[0];
        float sg = 1.0f / (1.0f + __expf(-tt));
        msk[tid] = (sg > 0.5f) ? 1.0f : 0.0f;
    }
    __syncthreads();

    // --- vectorized periphery conv + masked select: 4 outputs/thread/iter ---
    const float pr0 = periphery[0], pr1 = periphery[1], pr2 = periphery[2],
                pr3 = periphery[3], pr4 = periphery[4], pr5 = periphery[5],
                pr6 = periphery[6], pr7 = periphery[7];
    float* ob = out + (size_t)b * OO * HWSZ;

    for (int i = tid; i < OO * NOUT / 4; i += NTHR) {   // 2048/384 = 5.33 iters
        const int o   = i >> 5;
        const int pg  = i & 31;
        const int ty  = pg >> 2;        // output row 0..7
        const int tx0 = (pg & 3) * 4;   // output col base 0,4,8,12
        const float* zo = zs + o * LDZ;

        // halo rows ty, ty+1, ty+2; halo cols tx0 .. tx0+5 (all float2-aligned)
        const int rb = ty * HX + tx0;
        float2 t01 = *(const float2*)(zo + rb);
        float2 t23 = *(const float2*)(zo + rb + 2);
        float2 t45 = *(const float2*)(zo + rb + 4);
        float2 m01 = *(const float2*)(zo + rb + HX);
        float2 m23 = *(const float2*)(zo + rb + HX + 2);
        float2 m45 = *(const float2*)(zo + rb + HX + 4);
        float2 b01 = *(const float2*)(zo + rb + 2 * HX);
        float2 b23 = *(const float2*)(zo + rb + 2 * HX + 2);
        float2 b45 = *(const float2*)(zo + rb + 2 * HX + 4);

        const float tv[6] = {t01.x, t01.y, t23.x, t23.y, t45.x, t45.y};
        const float mv[6] = {m01.x, m01.y, m23.x, m23.y, m45.x, m45.y};
        const float bv[6] = {b01.x, b01.y, b23.x, b23.y, b45.x, b45.y};

        float4 mk4 = *(const float4*)(msk + ty * TX + tx0);
        const float mks[4] = {mk4.x, mk4.y, mk4.z, mk4.w};

        float4 res;
        float* rp = (float*)&res;
#pragma unroll
        for (int j = 0; j < 4; j++) {
            float a;
            a = pr0 * tv[j];
            a = fmaf(pr1, tv[j + 1], a);
            a = fmaf(pr2, tv[j + 2], a);
            a = fmaf(pr3, mv[j], a);
            a = fmaf(pr4, mv[j + 2], a);
            a = fmaf(pr5, bv[j], a);
            a = fmaf(pr6, bv[j + 1], a);
            a = fmaf(pr7, bv[j + 2], a);
            rp[j] = (mks[j] > 0.5f) ? a : mv[j + 1];
        }
        __stcg((float4*)&ob[(size_t)o * HWSZ + (size_t)(by0 + ty) * WW + bx0 + tx0],
               res);
    }
}

extern "C" void kernel_launch(void* const* d_in, const int* in_sizes, int n_in,
                              void* d_out, int out_size) {
    const float* x    = (const float*)d_in[0];
    const float* core = (const float*)d_in[1];
    const float* peri = (const float*)d_in[2];
    const float* thr  = (const float*)d_in[3];
    const float* scl  = (const float*)d_in[4];
    float* out = (float*)d_out;

    cudaFuncSetAttribute(spconv_mma3_kernel,
                         cudaFuncAttributeMaxDynamicSharedMemorySize, SMEM_BYTES);

    dim3 grid(WW / TX, HH / TY, BB);   // 1024 CTAs
    spconv_mma3_kernel<<<grid, NTHR, SMEM_BYTES>>>(x, core, peri, thr, scl, out);
}